// round 8
// baseline (speedup 1.0000x reference)
#include <cuda_runtime.h>
#include <cstdint>

// Problem: x[2,200000,32] f32, pos[2,200000,3] f32, kernel[3,3,3,32,32] f32,
// bias[32] f32 -> out[2,32,66,66,66] f32.
#define NPART 400000
#define NPERB 200000
#define DD    66
#define HWP   4356
#define DHW   287496

// Channel-PERMUTED, channel-last scratch [2*DHW][32]:
//   position p = tig*8 + nb*2 + e   holds true channel c = 2*tig + e + 8*nb.
// This makes each mma fragment's (row, nb-pair) values a contiguous float4,
// so the epilogue REDs go straight from registers (no smem staging).
// Zero at module load; re-zeroed inside transpose_kernel for the next call.
__device__ float g_scratch[(size_t)2 * DHW * 32];          // 73.6 MB

// Pre-split kernel matrices, B[n=co][k=ci] per tap: hi and lo bf16.
__device__ __align__(16) unsigned short g_Bh[27][32][32];
__device__ __align__(16) unsigned short g_Bl[27][32][32];

// ---------------- helpers --------------------------------------------------
__device__ __forceinline__ unsigned short f2bf(float f) {
    unsigned short u; asm("cvt.rn.bf16.f32 %0, %1;" : "=h"(u) : "f"(f)); return u;
}
__device__ __forceinline__ float bf2f(unsigned short u) {
    return __uint_as_float(((uint32_t)u) << 16);
}
__device__ __forceinline__ uint32_t smem_u32(const void* p) {
    uint32_t a;
    asm("{ .reg .u64 t; cvta.to.shared.u64 t, %1; cvt.u32.u64 %0, t; }"
        : "=r"(a) : "l"(p));
    return a;
}
__device__ __forceinline__ void ldm4(uint32_t* r, uint32_t addr) {
    asm volatile("ldmatrix.sync.aligned.m8n8.x4.shared.b16 {%0,%1,%2,%3}, [%4];"
                 : "=r"(r[0]), "=r"(r[1]), "=r"(r[2]), "=r"(r[3]) : "r"(addr));
}
__device__ __forceinline__ void mma_bf16(float* d, const uint32_t* a,
                                         uint32_t b0, uint32_t b1) {
    asm volatile(
        "mma.sync.aligned.m16n8k16.row.col.f32.bf16.bf16.f32 "
        "{%0,%1,%2,%3}, {%4,%5,%6,%7}, {%8,%9}, {%0,%1,%2,%3};"
        : "+f"(d[0]), "+f"(d[1]), "+f"(d[2]), "+f"(d[3])
        : "r"(a[0]), "r"(a[1]), "r"(a[2]), "r"(a[3]), "r"(b0), "r"(b1));
}

// ---------------------------------------------------------------------------
// Prebuild: split kernel into bf16 hi/lo, transposed to B[n=co][k=ci].
// ---------------------------------------------------------------------------
__global__ void prebuild_kernel(const float* __restrict__ kern) {
    const int g = blockIdx.x;                 // 27
    for (int idx = threadIdx.x; idx < 1024; idx += 256) {
        const int co = idx >> 5, ci = idx & 31;
        const float f = kern[(size_t)g * 1024 + ci * 32 + co];
        const unsigned short hi = f2bf(f);
        g_Bh[g][co][ci] = hi;
        g_Bl[g][co][ci] = f2bf(f - bf2f(hi));
    }
}

// ---------------------------------------------------------------------------
// Main: CTA = 4 warps, warp = 32 particles. Per (oi,oj,ok): 3-term bf16-split
// MMA D[32p,32co], then bias+weight applied ON FRAGMENTS and RED'd straight
// to the permuted scratch (8 float4 REDs/thread, no staging, no syncwarp).
// ---------------------------------------------------------------------------
#define OFF_AH 0
#define OFF_AL 10240
#define OFF_BH 20480
#define OFF_BL 28160
#define OFF_WX 35840
#define OFF_WY 37376
#define OFF_WZ 38912
#define OFF_NB 40448
#define SMEM_BYTES 40960

__global__ __launch_bounds__(128) void main_kernel(
    const float* __restrict__ x,
    const float* __restrict__ pos,
    const float* __restrict__ bias)
{
    extern __shared__ __align__(16) char smem[];
    const int tid  = threadIdx.x;
    const int w    = tid >> 5;
    const int lane = tid & 31;
    const int gid  = lane >> 2;          // fragment row id
    const int tig  = lane & 3;           // thread-in-group (col pair)
    const int pid  = blockIdx.x * 128 + w * 32 + lane;
    const uint32_t sb = smem_u32(smem);

    // ---- stage A: x -> bf16 hi/lo rows (80B stride, conflict-free) ----
    {
        float xv[32];
        const float4* xp = reinterpret_cast<const float4*>(x + (size_t)pid * 32);
#pragma unroll
        for (int t = 0; t < 8; ++t) {
            const float4 v = xp[t];
            xv[4 * t] = v.x; xv[4 * t + 1] = v.y; xv[4 * t + 2] = v.z; xv[4 * t + 3] = v.w;
        }
        uint32_t hw[16], lw[16];
#pragma unroll
        for (int k = 0; k < 16; ++k) {
            const float f0 = xv[2 * k], f1 = xv[2 * k + 1];
            const unsigned short h0 = f2bf(f0), h1 = f2bf(f1);
            const unsigned short l0 = f2bf(f0 - bf2f(h0)), l1 = f2bf(f1 - bf2f(h1));
            hw[k] = (uint32_t)h0 | ((uint32_t)h1 << 16);
            lw[k] = (uint32_t)l0 | ((uint32_t)l1 << 16);
        }
        char* rH = smem + OFF_AH + (w * 32 + lane) * 80;
        char* rL = smem + OFF_AL + (w * 32 + lane) * 80;
#pragma unroll
        for (int c = 0; c < 4; ++c) {
            reinterpret_cast<uint4*>(rH)[c] = make_uint4(hw[4*c], hw[4*c+1], hw[4*c+2], hw[4*c+3]);
            reinterpret_cast<uint4*>(rL)[c] = make_uint4(lw[4*c], lw[4*c+1], lw[4*c+2], lw[4*c+3]);
        }
    }

    // ---- weights + node for own particle ----
    {
        const float px = pos[pid * 3 + 0] * 64.f;
        const float py = pos[pid * 3 + 1] * 64.f;
        const float pz = pos[pid * 3 + 2] * 64.f;
        const int bx = (int)px, by = (int)py, bz = (int)pz;
        const float fx = px - (float)bx - 0.5f;
        const float fy = py - (float)by - 0.5f;
        const float fz = pz - (float)bz - 0.5f;
        float* WX = reinterpret_cast<float*>(smem + OFF_WX) + w * 96;
        float* WY = reinterpret_cast<float*>(smem + OFF_WY) + w * 96;
        float* WZ = reinterpret_cast<float*>(smem + OFF_WZ) + w * 96;
        WX[lane]      = 0.5f * (0.5f - fx) * (0.5f - fx);
        WX[32 + lane] = 0.75f - fx * fx;
        WX[64 + lane] = 0.5f * (0.5f + fx) * (0.5f + fx);
        WY[lane]      = 0.5f * (0.5f - fy) * (0.5f - fy);
        WY[32 + lane] = 0.75f - fy * fy;
        WY[64 + lane] = 0.5f * (0.5f + fy) * (0.5f + fy);
        WZ[lane]      = 0.5f * (0.5f - fz) * (0.5f - fz);
        WZ[32 + lane] = 0.75f - fz * fz;
        WZ[64 + lane] = 0.5f * (0.5f + fz) * (0.5f + fz);
        const int b = (pid >= NPERB) ? 1 : 0;
        reinterpret_cast<int*>(smem + OFF_NB)[w * 32 + lane] =
            b * DHW + bx * HWP + by * DD + bz;
    }
    __syncthreads();

    // ---- per-lane constants ----
    float bias_r[4][2];
#pragma unroll
    for (int nb = 0; nb < 4; ++nb) {
        bias_r[nb][0] = bias[nb * 8 + 2 * tig];
        bias_r[nb][1] = bias[nb * 8 + 2 * tig + 1];
    }

    // ---- A fragments (persistent registers) ----
    uint32_t aH[2][2][4], aL[2][2][4];
#pragma unroll
    for (int mb = 0; mb < 2; ++mb)
#pragma unroll
        for (int ks = 0; ks < 2; ++ks) {
            const uint32_t off = (uint32_t)((w * 32 + mb * 16 + (lane & 15)) * 80
                                            + ks * 32 + (lane >> 4) * 16);
            ldm4(aH[mb][ks], sb + OFF_AH + off);
            ldm4(aL[mb][ks], sb + OFF_AL + off);
        }

    const float* WX  = reinterpret_cast<float*>(smem + OFF_WX) + w * 96;
    const float* WY  = reinterpret_cast<float*>(smem + OFF_WY) + w * 96;
    const float* WZ  = reinterpret_cast<float*>(smem + OFF_WZ) + w * 96;
    const int*   NBw = reinterpret_cast<int*>(smem + OFF_NB) + w * 32;

    // Node bases for this thread's 4 fragment rows (rows gid + 8i).
    int node_r[4];
#pragma unroll
    for (int i = 0; i < 4; ++i) node_r[i] = NBw[gid + 8 * i];

    for (int g = 0; g < 9; ++g) {
        const int oi = g / 3, oj = g % 3;

        // ---- stage B hi/lo for this group's 3 ok taps ----
        __syncthreads();
#pragma unroll
        for (int it = 0; it < 3; ++it) {
            const int idx = it * 128 + tid;
            const int okk = idx >> 7, r = idx & 127;
            const int co = r >> 2, ch = r & 3;
            const uint4* sh = reinterpret_cast<const uint4*>(&g_Bh[g * 3 + okk][co][0]);
            const uint4* sl = reinterpret_cast<const uint4*>(&g_Bl[g * 3 + okk][co][0]);
            reinterpret_cast<uint4*>(smem + OFF_BH + okk * 2560 + co * 80)[ch] = sh[ch];
            reinterpret_cast<uint4*>(smem + OFF_BL + okk * 2560 + co * 80)[ch] = sl[ch];
        }
        __syncthreads();

        float w12[4];
#pragma unroll
        for (int i = 0; i < 4; ++i) {
            const int p = gid + i * 8;
            w12[i] = WX[oi * 32 + p] * WY[oj * 32 + p];
        }

        for (int ok = 0; ok < 3; ++ok) {
            // ---- B fragments ----
            uint32_t bh[4][4], bl[4][4];
#pragma unroll
            for (int nb = 0; nb < 4; ++nb) {
                const uint32_t ba = sb + OFF_BH + (uint32_t)(ok * 2560
                                    + (nb * 8 + (lane & 7)) * 80 + (lane >> 3) * 16);
                ldm4(bh[nb], ba);
                ldm4(bl[nb], ba + (OFF_BL - OFF_BH));
            }

            // ---- 3-term split MMA ----
            float d[2][4][4];
#pragma unroll
            for (int mb = 0; mb < 2; ++mb)
#pragma unroll
                for (int nb = 0; nb < 4; ++nb) {
#pragma unroll
                    for (int q = 0; q < 4; ++q) d[mb][nb][q] = 0.f;
                    mma_bf16(d[mb][nb], aH[mb][0], bh[nb][0], bh[nb][1]);
                    mma_bf16(d[mb][nb], aH[mb][1], bh[nb][2], bh[nb][3]);
                    mma_bf16(d[mb][nb], aH[mb][0], bl[nb][0], bl[nb][1]);
                    mma_bf16(d[mb][nb], aH[mb][1], bl[nb][2], bl[nb][3]);
                    mma_bf16(d[mb][nb], aL[mb][0], bh[nb][0], bh[nb][1]);
                    mma_bf16(d[mb][nb], aL[mb][1], bh[nb][2], bh[nb][3]);
                }

            // ---- epilogue: bias+weight on fragments, direct float4 REDs ----
            // Permuted scratch: pos p = tig*8 + nb*2 + e <-> c = 2tig+e+8nb.
            const int obase = oi * HWP + oj * DD + ok;
#pragma unroll
            for (int mb = 0; mb < 2; ++mb)
#pragma unroll
                for (int h = 0; h < 2; ++h) {           // row = mb*16+gid+8h
                    const int  i   = mb * 2 + h;
                    const float w3 = w12[i] * WZ[ok * 32 + gid + i * 8];
                    const int  di  = 2 * h;             // d0/d1 vs d2/d3
                    float* base = g_scratch
                        + (size_t)(node_r[i] + obase) * 32 + tig * 8;
                    const float4 v0 = make_float4(
                        (d[mb][0][di]     + bias_r[0][0]) * w3,
                        (d[mb][0][di + 1] + bias_r[0][1]) * w3,
                        (d[mb][1][di]     + bias_r[1][0]) * w3,
                        (d[mb][1][di + 1] + bias_r[1][1]) * w3);
                    const float4 v1 = make_float4(
                        (d[mb][2][di]     + bias_r[2][0]) * w3,
                        (d[mb][2][di + 1] + bias_r[2][1]) * w3,
                        (d[mb][3][di]     + bias_r[3][0]) * w3,
                        (d[mb][3][di + 1] + bias_r[3][1]) * w3);
                    atomicAdd(reinterpret_cast<float4*>(base), v0);
                    atomicAdd(reinterpret_cast<float4*>(base + 4), v1);
                }
        }
    }
}

// ---------------------------------------------------------------------------
// Transpose + un-permute + re-zero:
//   out[(b*32 + chi(p))*DHW + nd] = scratch[b*DHW + nd][p];  scratch := 0.
//   chi(p) = 2*(p>>3) + (p&1) + 8*((p>>1)&3).
// ---------------------------------------------------------------------------
__global__ void transpose_kernel(float* __restrict__ out) {
    __shared__ float t[32][33];
    const int nd0 = blockIdx.x * 32;
    const int b   = blockIdx.y;
    const int tx  = threadIdx.x, ty = threadIdx.y;
#pragma unroll
    for (int k = 0; k < 4; ++k) {
        const int nd = nd0 + ty + k * 8;
        if (nd < DHW) {
            float* src = &g_scratch[((size_t)b * DHW + nd) * 32 + tx];
            t[ty + k * 8][tx] = *src;
            *src = 0.f;                       // re-zero for next call
        }
    }
    __syncthreads();
    const int nd = nd0 + tx;
    if (nd < DHW) {
#pragma unroll
        for (int k = 0; k < 4; ++k) {
            const int p = ty + k * 8;
            const int c = 2 * (p >> 3) + (p & 1) + 8 * ((p >> 1) & 3);
            out[((size_t)b * 32 + c) * DHW + nd] = t[tx][p];
        }
    }
}

// ---------------------------------------------------------------------------
extern "C" void kernel_launch(void* const* d_in, const int* in_sizes, int n_in,
                              void* d_out, int out_size)
{
    const float* x    = reinterpret_cast<const float*>(d_in[0]);
    const float* pos  = reinterpret_cast<const float*>(d_in[1]);
    const float* kern = reinterpret_cast<const float*>(d_in[2]);
    const float* bias = reinterpret_cast<const float*>(d_in[3]);
    float* out = reinterpret_cast<float*>(d_out);

    prebuild_kernel<<<27, 256>>>(kern);
    main_kernel<<<NPART / 128, 128, SMEM_BYTES>>>(x, pos, bias);
    transpose_kernel<<<dim3((DHW + 31) / 32, 2), dim3(32, 8)>>>(out);
}

// round 11
// speedup vs baseline: 1.0758x; 1.0758x over previous
#include <cuda_runtime.h>
#include <cstdint>

// Problem: x[2,200000,32] f32, pos[2,200000,3] f32, kernel[3,3,3,32,32] f32,
// bias[32] f32 -> out[2,32,66,66,66] f32.
#define NPART 400000
#define NPERB 200000
#define DD    66
#define HWP   4356
#define DHW   287496
#define NWRP  8              // warps per CTA
#define CTAT  (NWRP * 32)    // 256 threads
#define NBLK  ((NPART + CTAT - 1) / CTAT)   // 1563 (last block partial!)

// Channel-last scratch [2*DHW][32]; zero at module load, re-zeroed inside
// transpose_kernel for the next call.
__device__ float g_scratch[(size_t)2 * DHW * 32];          // 73.6 MB

// Pre-split kernel matrices, B[n=co][k=ci] per tap: hi and lo bf16.
__device__ __align__(16) unsigned short g_Bh[27][32][32];
__device__ __align__(16) unsigned short g_Bl[27][32][32];

// ---------------- helpers --------------------------------------------------
__device__ __forceinline__ unsigned short f2bf(float f) {
    unsigned short u; asm("cvt.rn.bf16.f32 %0, %1;" : "=h"(u) : "f"(f)); return u;
}
__device__ __forceinline__ float bf2f(unsigned short u) {
    return __uint_as_float(((uint32_t)u) << 16);
}
__device__ __forceinline__ uint32_t smem_u32(const void* p) {
    uint32_t a;
    asm("{ .reg .u64 t; cvta.to.shared.u64 t, %1; cvt.u32.u64 %0, t; }"
        : "=r"(a) : "l"(p));
    return a;
}
__device__ __forceinline__ void ldm4(uint32_t* r, uint32_t addr) {
    asm volatile("ldmatrix.sync.aligned.m8n8.x4.shared.b16 {%0,%1,%2,%3}, [%4];"
                 : "=r"(r[0]), "=r"(r[1]), "=r"(r[2]), "=r"(r[3]) : "r"(addr));
}
__device__ __forceinline__ void mma_bf16(float* d, const uint32_t* a,
                                         uint32_t b0, uint32_t b1) {
    asm volatile(
        "mma.sync.aligned.m16n8k16.row.col.f32.bf16.bf16.f32 "
        "{%0,%1,%2,%3}, {%4,%5,%6,%7}, {%8,%9}, {%0,%1,%2,%3};"
        : "+f"(d[0]), "+f"(d[1]), "+f"(d[2]), "+f"(d[3])
        : "r"(a[0]), "r"(a[1]), "r"(a[2]), "r"(a[3]), "r"(b0), "r"(b1));
}

// ---------------------------------------------------------------------------
// Prebuild: split kernel into bf16 hi/lo, transposed to B[n=co][k=ci].
// ---------------------------------------------------------------------------
__global__ void prebuild_kernel(const float* __restrict__ kern) {
    const int g = blockIdx.x;                 // 27
    for (int idx = threadIdx.x; idx < 1024; idx += 256) {
        const int co = idx >> 5, ci = idx & 31;
        const float f = kern[(size_t)g * 1024 + ci * 32 + co];
        const unsigned short hi = f2bf(f);
        g_Bh[g][co][ci] = hi;
        g_Bl[g][co][ci] = f2bf(f - bf2f(hi));
    }
}

// ---------------------------------------------------------------------------
// Main (R7 logic, 8 warps/CTA): warp = 32 particles. Per (oi,oj,ok): 3-term
// bf16-split MMA D[32p,32co]; epilogue stages weighted fragments to pb[p][co]
// then 8 coalesced float4 REDs (each RED: 4 particles x one FULL 128B line).
// Tail lanes (pid >= NPART): clamp loads, zero weights -> contribute 0.
// ---------------------------------------------------------------------------
#define OFF_AH 0
#define OFF_AL 20480
#define OFF_BH 40960
#define OFF_BL 48640
#define OFF_WX 56320
#define OFF_WY 59392
#define OFF_WZ 62464
#define OFF_NB 65536
#define OFF_PB 66560
#define SMEM_BYTES (OFF_PB + NWRP * 32 * 36 * 4)   // 103424

__global__ __launch_bounds__(CTAT) void main_kernel(
    const float* __restrict__ x,
    const float* __restrict__ pos,
    const float* __restrict__ bias)
{
    extern __shared__ __align__(16) char smem[];
    const int tid  = threadIdx.x;
    const int w    = tid >> 5;
    const int lane = tid & 31;
    const int gid  = lane >> 2;          // fragment row id
    const int tig  = lane & 3;           // thread-in-group (col pair)
    const int pid0 = blockIdx.x * CTAT + w * 32 + lane;
    const float vmask = (pid0 < NPART) ? 1.f : 0.f;   // tail-lane kill switch
    const int pid  = (pid0 < NPART) ? pid0 : (NPART - 1);
    const uint32_t sb = smem_u32(smem);

    // ---- stage A: x -> bf16 hi/lo rows (80B stride, conflict-free) ----
    {
        float xv[32];
        const float4* xp = reinterpret_cast<const float4*>(x + (size_t)pid * 32);
#pragma unroll
        for (int t = 0; t < 8; ++t) {
            const float4 v = xp[t];
            xv[4 * t] = v.x; xv[4 * t + 1] = v.y; xv[4 * t + 2] = v.z; xv[4 * t + 3] = v.w;
        }
        uint32_t hw[16], lw[16];
#pragma unroll
        for (int k = 0; k < 16; ++k) {
            const float f0 = xv[2 * k], f1 = xv[2 * k + 1];
            const unsigned short h0 = f2bf(f0), h1 = f2bf(f1);
            const unsigned short l0 = f2bf(f0 - bf2f(h0)), l1 = f2bf(f1 - bf2f(h1));
            hw[k] = (uint32_t)h0 | ((uint32_t)h1 << 16);
            lw[k] = (uint32_t)l0 | ((uint32_t)l1 << 16);
        }
        char* rH = smem + OFF_AH + (w * 32 + lane) * 80;
        char* rL = smem + OFF_AL + (w * 32 + lane) * 80;
#pragma unroll
        for (int c = 0; c < 4; ++c) {
            reinterpret_cast<uint4*>(rH)[c] = make_uint4(hw[4*c], hw[4*c+1], hw[4*c+2], hw[4*c+3]);
            reinterpret_cast<uint4*>(rL)[c] = make_uint4(lw[4*c], lw[4*c+1], lw[4*c+2], lw[4*c+3]);
        }
    }

    // ---- weights + node for own particle (weights zeroed on tail lanes) ----
    {
        const float px = pos[pid * 3 + 0] * 64.f;
        const float py = pos[pid * 3 + 1] * 64.f;
        const float pz = pos[pid * 3 + 2] * 64.f;
        const int bx = (int)px, by = (int)py, bz = (int)pz;
        const float fx = px - (float)bx - 0.5f;
        const float fy = py - (float)by - 0.5f;
        const float fz = pz - (float)bz - 0.5f;
        float* WX = reinterpret_cast<float*>(smem + OFF_WX) + w * 96;
        float* WY = reinterpret_cast<float*>(smem + OFF_WY) + w * 96;
        float* WZ = reinterpret_cast<float*>(smem + OFF_WZ) + w * 96;
        WX[lane]      = vmask * 0.5f * (0.5f - fx) * (0.5f - fx);
        WX[32 + lane] = vmask * (0.75f - fx * fx);
        WX[64 + lane] = vmask * 0.5f * (0.5f + fx) * (0.5f + fx);
        WY[lane]      = 0.5f * (0.5f - fy) * (0.5f - fy);
        WY[32 + lane] = 0.75f - fy * fy;
        WY[64 + lane] = 0.5f * (0.5f + fy) * (0.5f + fy);
        WZ[lane]      = 0.5f * (0.5f - fz) * (0.5f - fz);
        WZ[32 + lane] = 0.75f - fz * fz;
        WZ[64 + lane] = 0.5f * (0.5f + fz) * (0.5f + fz);
        const int b = (pid >= NPERB) ? 1 : 0;
        reinterpret_cast<int*>(smem + OFF_NB)[w * 32 + lane] =
            b * DHW + bx * HWP + by * DD + bz;
    }
    __syncthreads();

    // ---- per-lane constants ----
    float bias_r[4][2];
#pragma unroll
    for (int nb = 0; nb < 4; ++nb) {
        bias_r[nb][0] = bias[nb * 8 + 2 * tig];
        bias_r[nb][1] = bias[nb * 8 + 2 * tig + 1];
    }

    // ---- A fragments (persistent registers) ----
    uint32_t aH[2][2][4], aL[2][2][4];
#pragma unroll
    for (int mb = 0; mb < 2; ++mb)
#pragma unroll
        for (int ks = 0; ks < 2; ++ks) {
            const uint32_t off = (uint32_t)((w * 32 + mb * 16 + (lane & 15)) * 80
                                            + ks * 32 + (lane >> 4) * 16);
            ldm4(aH[mb][ks], sb + OFF_AH + off);
            ldm4(aL[mb][ks], sb + OFF_AL + off);
        }

    const float* WX  = reinterpret_cast<float*>(smem + OFF_WX) + w * 96;
    const float* WY  = reinterpret_cast<float*>(smem + OFF_WY) + w * 96;
    const float* WZ  = reinterpret_cast<float*>(smem + OFF_WZ) + w * 96;
    const int*   NBw = reinterpret_cast<int*>(smem + OFF_NB) + w * 32;
    float* const pbw = reinterpret_cast<float*>(smem + OFF_PB) + w * 1152;  // 32*36

    for (int g = 0; g < 9; ++g) {
        const int oi = g / 3, oj = g % 3;

        // ---- stage B hi/lo for this group's 3 ok taps (CTA-amortized) ----
        __syncthreads();
#pragma unroll
        for (int it = 0; it < 3; ++it) {
            const int idx = it * CTAT + tid;         // 768 uint4 chunks total
            const int side = (idx >= 384) ? 1 : 0;
            const int r2 = idx - side * 384;         // true mod-384
            const int okk = r2 >> 7, r = r2 & 127;
            const int co = r >> 2, ch = r & 3;
            const uint4* src = side
                ? reinterpret_cast<const uint4*>(&g_Bl[g * 3 + okk][co][0])
                : reinterpret_cast<const uint4*>(&g_Bh[g * 3 + okk][co][0]);
            char* dst = smem + (side ? OFF_BL : OFF_BH) + okk * 2560 + co * 80;
            reinterpret_cast<uint4*>(dst)[ch] = src[ch];
        }
        __syncthreads();

        float w12[4];
#pragma unroll
        for (int i = 0; i < 4; ++i) {
            const int p = gid + i * 8;
            w12[i] = WX[oi * 32 + p] * WY[oj * 32 + p];
        }

        for (int ok = 0; ok < 3; ++ok) {
            // ---- B fragments ----
            uint32_t bh[4][4], bl[4][4];
#pragma unroll
            for (int nb = 0; nb < 4; ++nb) {
                const uint32_t ba = sb + OFF_BH + (uint32_t)(ok * 2560
                                    + (nb * 8 + (lane & 7)) * 80 + (lane >> 3) * 16);
                ldm4(bh[nb], ba);
                ldm4(bl[nb], ba + (OFF_BL - OFF_BH));
            }

            // ---- 3-term split MMA ----
            float d[2][4][4];
#pragma unroll
            for (int mb = 0; mb < 2; ++mb)
#pragma unroll
                for (int nb = 0; nb < 4; ++nb) {
#pragma unroll
                    for (int q = 0; q < 4; ++q) d[mb][nb][q] = 0.f;
                    mma_bf16(d[mb][nb], aH[mb][0], bh[nb][0], bh[nb][1]);
                    mma_bf16(d[mb][nb], aH[mb][1], bh[nb][2], bh[nb][3]);
                    mma_bf16(d[mb][nb], aH[mb][0], bl[nb][0], bl[nb][1]);
                    mma_bf16(d[mb][nb], aH[mb][1], bl[nb][2], bl[nb][3]);
                    mma_bf16(d[mb][nb], aL[mb][0], bh[nb][0], bh[nb][1]);
                    mma_bf16(d[mb][nb], aL[mb][1], bh[nb][2], bh[nb][3]);
                }

            float w3[4];
#pragma unroll
            for (int i = 0; i < 4; ++i)
                w3[i] = w12[i] * WZ[ok * 32 + gid + i * 8];

            // ---- weighted fragments -> pb [p][co] (R7-proven staging) ----
#pragma unroll
            for (int mb = 0; mb < 2; ++mb)
#pragma unroll
                for (int nb = 0; nb < 4; ++nb) {
                    const int r0 = mb * 16 + gid;
                    const int c  = nb * 8 + 2 * tig;
                    float2 v0, v1;
                    v0.x = (d[mb][nb][0] + bias_r[nb][0]) * w3[mb * 2];
                    v0.y = (d[mb][nb][1] + bias_r[nb][1]) * w3[mb * 2];
                    v1.x = (d[mb][nb][2] + bias_r[nb][0]) * w3[mb * 2 + 1];
                    v1.y = (d[mb][nb][3] + bias_r[nb][1]) * w3[mb * 2 + 1];
                    *reinterpret_cast<float2*>(&pbw[r0 * 36 + c])       = v0;
                    *reinterpret_cast<float2*>(&pbw[(r0 + 8) * 36 + c]) = v1;
                }
            __syncwarp();

            // ---- coalesced float4 REDs (4 particles x full 128B line each) ----
            const int obase = oi * HWP + oj * DD + ok;
#pragma unroll
            for (int i = 0; i < 8; ++i) {
                const int f = i * 32 + lane;
                const int p = f >> 3, q = f & 7;
                const int nd = NBw[p] + obase;
                const float4 v = *reinterpret_cast<const float4*>(&pbw[p * 36 + q * 4]);
                atomicAdd(reinterpret_cast<float4*>(
                              g_scratch + (size_t)nd * 32 + q * 4), v);
            }
            __syncwarp();
        }
    }
}

// ---------------------------------------------------------------------------
// Transpose scratch [b][node][c] -> out [b][c][node], re-zeroing scratch.
// ---------------------------------------------------------------------------
__global__ void transpose_kernel(float* __restrict__ out) {
    __shared__ float t[32][33];
    const int nd0 = blockIdx.x * 32;
    const int b   = blockIdx.y;
    const int tx  = threadIdx.x, ty = threadIdx.y;
#pragma unroll
    for (int k = 0; k < 4; ++k) {
        const int nd = nd0 + ty + k * 8;
        if (nd < DHW) {
            float* src = &g_scratch[((size_t)b * DHW + nd) * 32 + tx];
            t[ty + k * 8][tx] = *src;
            *src = 0.f;                       // re-zero for next call
        }
    }
    __syncthreads();
    const int nd = nd0 + tx;
    if (nd < DHW) {
#pragma unroll
        for (int k = 0; k < 4; ++k) {
            const int c = ty + k * 8;
            out[((size_t)b * 32 + c) * DHW + nd] = t[tx][c];
        }
    }
}

// ---------------------------------------------------------------------------
extern "C" void kernel_launch(void* const* d_in, const int* in_sizes, int n_in,
                              void* d_out, int out_size)
{
    const float* x    = reinterpret_cast<const float*>(d_in[0]);
    const float* pos  = reinterpret_cast<const float*>(d_in[1]);
    const float* kern = reinterpret_cast<const float*>(d_in[2]);
    const float* bias = reinterpret_cast<const float*>(d_in[3]);
    float* out = reinterpret_cast<float*>(d_out);

    static int attr_done = 0;
    if (!attr_done) {
        cudaFuncSetAttribute(main_kernel,
                             cudaFuncAttributeMaxDynamicSharedMemorySize,
                             SMEM_BYTES);
        attr_done = 1;
    }

    prebuild_kernel<<<27, 256>>>(kern);
    main_kernel<<<NBLK, CTAT, SMEM_BYTES>>>(x, pos, bias);
    transpose_kernel<<<dim3((DHW + 31) / 32, 2), dim3(32, 8)>>>(out);
}

// round 12
// speedup vs baseline: 1.0895x; 1.0127x over previous
#include <cuda_runtime.h>
#include <cstdint>

// Problem: x[2,200000,32] f32, pos[2,200000,3] f32, kernel[3,3,3,32,32] f32,
// bias[32] f32 -> out[2,32,66,66,66] f32.
#define NPART 400000
#define NPERB 200000
#define DD    66
#define HWP   4356
#define DHW   287496

// Channel-last scratch [2*DHW][32]; zero at module load, re-zeroed inside
// transpose_kernel for the next call.
__device__ float g_scratch[(size_t)2 * DHW * 32];          // 73.6 MB

// Pre-split kernel matrices, B[n=co][k=ci] per tap: hi and lo bf16.
__device__ __align__(16) unsigned short g_Bh[27][32][32];
__device__ __align__(16) unsigned short g_Bl[27][32][32];

// ---------------- helpers --------------------------------------------------
__device__ __forceinline__ unsigned short f2bf(float f) {
    unsigned short u; asm("cvt.rn.bf16.f32 %0, %1;" : "=h"(u) : "f"(f)); return u;
}
__device__ __forceinline__ float bf2f(unsigned short u) {
    return __uint_as_float(((uint32_t)u) << 16);
}
__device__ __forceinline__ uint32_t smem_u32(const void* p) {
    uint32_t a;
    asm("{ .reg .u64 t; cvta.to.shared.u64 t, %1; cvt.u32.u64 %0, t; }"
        : "=r"(a) : "l"(p));
    return a;
}
__device__ __forceinline__ void ldm4(uint32_t* r, uint32_t addr) {
    asm volatile("ldmatrix.sync.aligned.m8n8.x4.shared.b16 {%0,%1,%2,%3}, [%4];"
                 : "=r"(r[0]), "=r"(r[1]), "=r"(r[2]), "=r"(r[3]) : "r"(addr));
}
__device__ __forceinline__ void mma_bf16(float* d, const uint32_t* a,
                                         uint32_t b0, uint32_t b1) {
    asm volatile(
        "mma.sync.aligned.m16n8k16.row.col.f32.bf16.bf16.f32 "
        "{%0,%1,%2,%3}, {%4,%5,%6,%7}, {%8,%9}, {%0,%1,%2,%3};"
        : "+f"(d[0]), "+f"(d[1]), "+f"(d[2]), "+f"(d[3])
        : "r"(a[0]), "r"(a[1]), "r"(a[2]), "r"(a[3]), "r"(b0), "r"(b1));
}

// ---------------------------------------------------------------------------
// Prebuild: split kernel into bf16 hi/lo, transposed to B[n=co][k=ci].
// ---------------------------------------------------------------------------
__global__ void prebuild_kernel(const float* __restrict__ kern) {
    const int g = blockIdx.x;                 // 27
    for (int idx = threadIdx.x; idx < 1024; idx += 256) {
        const int co = idx >> 5, ci = idx & 31;
        const float f = kern[(size_t)g * 1024 + ci * 32 + co];
        const unsigned short hi = f2bf(f);
        g_Bh[g][co][ci] = hi;
        g_Bl[g][co][ci] = f2bf(f - bf2f(hi));
    }
}

// ---------------------------------------------------------------------------
// Main (exact R7 configuration): CTA = 4 warps, warp = 32 particles.
// Per (oi,oj,ok): 3-term bf16-split MMA D[32p,32co]; epilogue stages weighted
// fragments to pb[p][co], then 8 coalesced float4 REDs (each RED: 4 particles
// x one FULL 128B line).
// ---------------------------------------------------------------------------
#define OFF_AH 0
#define OFF_AL 10240
#define OFF_BH 20480
#define OFF_BL 28160
#define OFF_WX 35840
#define OFF_WY 37376
#define OFF_WZ 38912
#define OFF_NB 40448
#define OFF_PB 40960
#define SMEM_BYTES (OFF_PB + 4 * 32 * 36 * 4)   // 59392

__global__ __launch_bounds__(128) void main_kernel(
    const float* __restrict__ x,
    const float* __restrict__ pos,
    const float* __restrict__ bias)
{
    extern __shared__ __align__(16) char smem[];
    const int tid  = threadIdx.x;
    const int w    = tid >> 5;
    const int lane = tid & 31;
    const int gid  = lane >> 2;          // fragment row id
    const int tig  = lane & 3;           // thread-in-group (col pair)
    const int pid  = blockIdx.x * 128 + w * 32 + lane;
    const uint32_t sb = smem_u32(smem);

    // ---- stage A: x -> bf16 hi/lo rows (80B stride, conflict-free) ----
    {
        float xv[32];
        const float4* xp = reinterpret_cast<const float4*>(x + (size_t)pid * 32);
#pragma unroll
        for (int t = 0; t < 8; ++t) {
            const float4 v = xp[t];
            xv[4 * t] = v.x; xv[4 * t + 1] = v.y; xv[4 * t + 2] = v.z; xv[4 * t + 3] = v.w;
        }
        uint32_t hw[16], lw[16];
#pragma unroll
        for (int k = 0; k < 16; ++k) {
            const float f0 = xv[2 * k], f1 = xv[2 * k + 1];
            const unsigned short h0 = f2bf(f0), h1 = f2bf(f1);
            const unsigned short l0 = f2bf(f0 - bf2f(h0)), l1 = f2bf(f1 - bf2f(h1));
            hw[k] = (uint32_t)h0 | ((uint32_t)h1 << 16);
            lw[k] = (uint32_t)l0 | ((uint32_t)l1 << 16);
        }
        char* rH = smem + OFF_AH + (w * 32 + lane) * 80;
        char* rL = smem + OFF_AL + (w * 32 + lane) * 80;
#pragma unroll
        for (int c = 0; c < 4; ++c) {
            reinterpret_cast<uint4*>(rH)[c] = make_uint4(hw[4*c], hw[4*c+1], hw[4*c+2], hw[4*c+3]);
            reinterpret_cast<uint4*>(rL)[c] = make_uint4(lw[4*c], lw[4*c+1], lw[4*c+2], lw[4*c+3]);
        }
    }

    // ---- weights + node for own particle ----
    {
        const float px = pos[pid * 3 + 0] * 64.f;
        const float py = pos[pid * 3 + 1] * 64.f;
        const float pz = pos[pid * 3 + 2] * 64.f;
        const int bx = (int)px, by = (int)py, bz = (int)pz;
        const float fx = px - (float)bx - 0.5f;
        const float fy = py - (float)by - 0.5f;
        const float fz = pz - (float)bz - 0.5f;
        float* WX = reinterpret_cast<float*>(smem + OFF_WX) + w * 96;
        float* WY = reinterpret_cast<float*>(smem + OFF_WY) + w * 96;
        float* WZ = reinterpret_cast<float*>(smem + OFF_WZ) + w * 96;
        WX[lane]      = 0.5f * (0.5f - fx) * (0.5f - fx);
        WX[32 + lane] = 0.75f - fx * fx;
        WX[64 + lane] = 0.5f * (0.5f + fx) * (0.5f + fx);
        WY[lane]      = 0.5f * (0.5f - fy) * (0.5f - fy);
        WY[32 + lane] = 0.75f - fy * fy;
        WY[64 + lane] = 0.5f * (0.5f + fy) * (0.5f + fy);
        WZ[lane]      = 0.5f * (0.5f - fz) * (0.5f - fz);
        WZ[32 + lane] = 0.75f - fz * fz;
        WZ[64 + lane] = 0.5f * (0.5f + fz) * (0.5f + fz);
        const int b = (pid >= NPERB) ? 1 : 0;
        reinterpret_cast<int*>(smem + OFF_NB)[w * 32 + lane] =
            b * DHW + bx * HWP + by * DD + bz;
    }
    __syncthreads();

    // ---- per-lane constants ----
    float bias_r[4][2];
#pragma unroll
    for (int nb = 0; nb < 4; ++nb) {
        bias_r[nb][0] = bias[nb * 8 + 2 * tig];
        bias_r[nb][1] = bias[nb * 8 + 2 * tig + 1];
    }

    // ---- A fragments (persistent registers) ----
    uint32_t aH[2][2][4], aL[2][2][4];
#pragma unroll
    for (int mb = 0; mb < 2; ++mb)
#pragma unroll
        for (int ks = 0; ks < 2; ++ks) {
            const uint32_t off = (uint32_t)((w * 32 + mb * 16 + (lane & 15)) * 80
                                            + ks * 32 + (lane >> 4) * 16);
            ldm4(aH[mb][ks], sb + OFF_AH + off);
            ldm4(aL[mb][ks], sb + OFF_AL + off);
        }

    const float* WX  = reinterpret_cast<float*>(smem + OFF_WX) + w * 96;
    const float* WY  = reinterpret_cast<float*>(smem + OFF_WY) + w * 96;
    const float* WZ  = reinterpret_cast<float*>(smem + OFF_WZ) + w * 96;
    const int*   NBw = reinterpret_cast<int*>(smem + OFF_NB) + w * 32;
    float* const pbw = reinterpret_cast<float*>(smem + OFF_PB) + w * 1152;  // 32*36

    for (int g = 0; g < 9; ++g) {
        const int oi = g / 3, oj = g % 3;

        // ---- stage B hi/lo for this group's 3 ok taps ----
        __syncthreads();
#pragma unroll
        for (int it = 0; it < 3; ++it) {
            const int idx = it * 128 + tid;
            const int okk = idx >> 7, r = idx & 127;
            const int co = r >> 2, ch = r & 3;
            const uint4* sh = reinterpret_cast<const uint4*>(&g_Bh[g * 3 + okk][co][0]);
            const uint4* sl = reinterpret_cast<const uint4*>(&g_Bl[g * 3 + okk][co][0]);
            reinterpret_cast<uint4*>(smem + OFF_BH + okk * 2560 + co * 80)[ch] = sh[ch];
            reinterpret_cast<uint4*>(smem + OFF_BL + okk * 2560 + co * 80)[ch] = sl[ch];
        }
        __syncthreads();

        float w12[4];
#pragma unroll
        for (int i = 0; i < 4; ++i) {
            const int p = gid + i * 8;
            w12[i] = WX[oi * 32 + p] * WY[oj * 32 + p];
        }

        for (int ok = 0; ok < 3; ++ok) {
            // ---- B fragments ----
            uint32_t bh[4][4], bl[4][4];
#pragma unroll
            for (int nb = 0; nb < 4; ++nb) {
                const uint32_t ba = sb + OFF_BH + (uint32_t)(ok * 2560
                                    + (nb * 8 + (lane & 7)) * 80 + (lane >> 3) * 16);
                ldm4(bh[nb], ba);
                ldm4(bl[nb], ba + (OFF_BL - OFF_BH));
            }

            // ---- 3-term split MMA ----
            float d[2][4][4];
#pragma unroll
            for (int mb = 0; mb < 2; ++mb)
#pragma unroll
                for (int nb = 0; nb < 4; ++nb) {
#pragma unroll
                    for (int q = 0; q < 4; ++q) d[mb][nb][q] = 0.f;
                    mma_bf16(d[mb][nb], aH[mb][0], bh[nb][0], bh[nb][1]);
                    mma_bf16(d[mb][nb], aH[mb][1], bh[nb][2], bh[nb][3]);
                    mma_bf16(d[mb][nb], aH[mb][0], bl[nb][0], bl[nb][1]);
                    mma_bf16(d[mb][nb], aH[mb][1], bl[nb][2], bl[nb][3]);
                    mma_bf16(d[mb][nb], aL[mb][0], bh[nb][0], bh[nb][1]);
                    mma_bf16(d[mb][nb], aL[mb][1], bh[nb][2], bh[nb][3]);
                }

            float w3[4];
#pragma unroll
            for (int i = 0; i < 4; ++i)
                w3[i] = w12[i] * WZ[ok * 32 + gid + i * 8];

            // ---- weighted fragments -> pb [p][co] (R7-proven staging) ----
#pragma unroll
            for (int mb = 0; mb < 2; ++mb)
#pragma unroll
                for (int nb = 0; nb < 4; ++nb) {
                    const int r0 = mb * 16 + gid;
                    const int c  = nb * 8 + 2 * tig;
                    float2 v0, v1;
                    v0.x = (d[mb][nb][0] + bias_r[nb][0]) * w3[mb * 2];
                    v0.y = (d[mb][nb][1] + bias_r[nb][1]) * w3[mb * 2];
                    v1.x = (d[mb][nb][2] + bias_r[nb][0]) * w3[mb * 2 + 1];
                    v1.y = (d[mb][nb][3] + bias_r[nb][1]) * w3[mb * 2 + 1];
                    *reinterpret_cast<float2*>(&pbw[r0 * 36 + c])       = v0;
                    *reinterpret_cast<float2*>(&pbw[(r0 + 8) * 36 + c]) = v1;
                }
            __syncwarp();

            // ---- coalesced float4 REDs (4 particles x full 128B line each) ----
            const int obase = oi * HWP + oj * DD + ok;
#pragma unroll
            for (int i = 0; i < 8; ++i) {
                const int f = i * 32 + lane;
                const int p = f >> 3, q = f & 7;
                const int nd = NBw[p] + obase;
                const float4 v = *reinterpret_cast<const float4*>(&pbw[p * 36 + q * 4]);
                atomicAdd(reinterpret_cast<float4*>(
                              g_scratch + (size_t)nd * 32 + q * 4), v);
            }
            __syncwarp();
        }
    }
}

// ---------------------------------------------------------------------------
// Transpose scratch [b][node][c] -> out [b][c][node], re-zeroing scratch
// for the next call (replaces the standalone zero kernel).
// ---------------------------------------------------------------------------
__global__ void transpose_kernel(float* __restrict__ out) {
    __shared__ float t[32][33];
    const int nd0 = blockIdx.x * 32;
    const int b   = blockIdx.y;
    const int tx  = threadIdx.x, ty = threadIdx.y;
#pragma unroll
    for (int k = 0; k < 4; ++k) {
        const int nd = nd0 + ty + k * 8;
        if (nd < DHW) {
            float* src = &g_scratch[((size_t)b * DHW + nd) * 32 + tx];
            t[ty + k * 8][tx] = *src;
            *src = 0.f;                       // re-zero for next call
        }
    }
    __syncthreads();
    const int nd = nd0 + tx;
    if (nd < DHW) {
#pragma unroll
        for (int k = 0; k < 4; ++k) {
            const int c = ty + k * 8;
            out[((size_t)b * 32 + c) * DHW + nd] = t[tx][c];
        }
    }
}

// ---------------------------------------------------------------------------
extern "C" void kernel_launch(void* const* d_in, const int* in_sizes, int n_in,
                              void* d_out, int out_size)
{
    const float* x    = reinterpret_cast<const float*>(d_in[0]);
    const float* pos  = reinterpret_cast<const float*>(d_in[1]);
    const float* kern = reinterpret_cast<const float*>(d_in[2]);
    const float* bias = reinterpret_cast<const float*>(d_in[3]);
    float* out = reinterpret_cast<float*>(d_out);

    static int attr_done = 0;
    if (!attr_done) {
        cudaFuncSetAttribute(main_kernel,
                             cudaFuncAttributeMaxDynamicSharedMemorySize,
                             SMEM_BYTES);
        attr_done = 1;
    }

    prebuild_kernel<<<27, 256>>>(kern);
    main_kernel<<<NPART / 128, 128, SMEM_BYTES>>>(x, pos, bias);
    transpose_kernel<<<dim3((DHW + 31) / 32, 2), dim3(32, 8)>>>(out);
}

// round 13
// speedup vs baseline: 1.7758x; 1.6299x over previous
#include <cuda_runtime.h>
#include <cstdint>

// Problem: x[2,200000,32] f32, pos[2,200000,3] f32, kernel[3,3,3,32,32] f32,
// bias[32] f32 -> out[2,32,66,66,66] f32.
#define NPART 400000
#define NPERB 200000
#define DD    66
#define HWP   4356
#define DHW   287496

// Channel-last scratch [2*DHW][32]; zero at module load, re-zeroed at end of
// every launch by the standalone zero kernel (R7-proven configuration).
__device__ float g_scratch[(size_t)2 * DHW * 32];          // 73.6 MB

// Pre-split kernel matrices, B[n=co][k=ci] per tap: hi and lo bf16.
__device__ __align__(16) unsigned short g_Bh[27][32][32];
__device__ __align__(16) unsigned short g_Bl[27][32][32];

// ---------------- helpers --------------------------------------------------
__device__ __forceinline__ unsigned short f2bf(float f) {
    unsigned short u; asm("cvt.rn.bf16.f32 %0, %1;" : "=h"(u) : "f"(f)); return u;
}
__device__ __forceinline__ float bf2f(unsigned short u) {
    return __uint_as_float(((uint32_t)u) << 16);
}
__device__ __forceinline__ uint32_t smem_u32(const void* p) {
    uint32_t a;
    asm("{ .reg .u64 t; cvta.to.shared.u64 t, %1; cvt.u32.u64 %0, t; }"
        : "=r"(a) : "l"(p));
    return a;
}
__device__ __forceinline__ void ldm4(uint32_t* r, uint32_t addr) {
    asm volatile("ldmatrix.sync.aligned.m8n8.x4.shared.b16 {%0,%1,%2,%3}, [%4];"
                 : "=r"(r[0]), "=r"(r[1]), "=r"(r[2]), "=r"(r[3]) : "r"(addr));
}
__device__ __forceinline__ void mma_bf16(float* d, const uint32_t* a,
                                         uint32_t b0, uint32_t b1) {
    asm volatile(
        "mma.sync.aligned.m16n8k16.row.col.f32.bf16.bf16.f32 "
        "{%0,%1,%2,%3}, {%4,%5,%6,%7}, {%8,%9}, {%0,%1,%2,%3};"
        : "+f"(d[0]), "+f"(d[1]), "+f"(d[2]), "+f"(d[3])
        : "r"(a[0]), "r"(a[1]), "r"(a[2]), "r"(a[3]), "r"(b0), "r"(b1));
}

// ---------------------------------------------------------------------------
// Prebuild: split kernel into bf16 hi/lo, transposed to B[n=co][k=ci].
// ---------------------------------------------------------------------------
__global__ void prebuild_kernel(const float* __restrict__ kern) {
    const int g = blockIdx.x;                 // 27
    for (int idx = threadIdx.x; idx < 1024; idx += 256) {
        const int co = idx >> 5, ci = idx & 31;
        const float f = kern[(size_t)g * 1024 + ci * 32 + co];
        const unsigned short hi = f2bf(f);
        g_Bh[g][co][ci] = hi;
        g_Bl[g][co][ci] = f2bf(f - bf2f(hi));
    }
}

// ---------------------------------------------------------------------------
// Main kernel: CTA = 128 threads = 4 warps, each warp owns 32 particles.
// Per (oi,oj,ok): 3-term bf16-split MMA D[32p,32co]; epilogue: (d+bias)*w3 on
// fragments -> pb smem [p][co] -> 8 coalesced float4 REDs into g_scratch.
// ---------------------------------------------------------------------------
#define OFF_AH 0
#define OFF_AL 10240
#define OFF_BH 20480
#define OFF_BL 28160
#define OFF_WX 35840
#define OFF_WY 37376
#define OFF_WZ 38912
#define OFF_NB 40448
#define OFF_PB 40960
#define SMEM_BYTES (OFF_PB + 4 * 32 * 36 * 4)   // 59392

__global__ __launch_bounds__(128) void main_kernel(
    const float* __restrict__ x,
    const float* __restrict__ pos,
    const float* __restrict__ bias)
{
    extern __shared__ __align__(16) char smem[];
    const int tid  = threadIdx.x;
    const int w    = tid >> 5;
    const int lane = tid & 31;
    const int gid  = lane >> 2;          // fragment group id (row)
    const int tig  = lane & 3;           // thread-in-group (col pair)
    const int pid  = blockIdx.x * 128 + w * 32 + lane;
    const uint32_t sb = smem_u32(smem);

    // ---- stage A: x -> bf16 hi/lo rows (80B stride, conflict-free) ----
    {
        float xv[32];
        const float4* xp = reinterpret_cast<const float4*>(x + (size_t)pid * 32);
#pragma unroll
        for (int t = 0; t < 8; ++t) {
            const float4 v = xp[t];
            xv[4 * t] = v.x; xv[4 * t + 1] = v.y; xv[4 * t + 2] = v.z; xv[4 * t + 3] = v.w;
        }
        uint32_t hw[16], lw[16];
#pragma unroll
        for (int k = 0; k < 16; ++k) {
            const float f0 = xv[2 * k], f1 = xv[2 * k + 1];
            const unsigned short h0 = f2bf(f0), h1 = f2bf(f1);
            const unsigned short l0 = f2bf(f0 - bf2f(h0)), l1 = f2bf(f1 - bf2f(h1));
            hw[k] = (uint32_t)h0 | ((uint32_t)h1 << 16);
            lw[k] = (uint32_t)l0 | ((uint32_t)l1 << 16);
        }
        char* rH = smem + OFF_AH + (w * 32 + lane) * 80;
        char* rL = smem + OFF_AL + (w * 32 + lane) * 80;
#pragma unroll
        for (int c = 0; c < 4; ++c) {
            reinterpret_cast<uint4*>(rH)[c] = make_uint4(hw[4*c], hw[4*c+1], hw[4*c+2], hw[4*c+3]);
            reinterpret_cast<uint4*>(rL)[c] = make_uint4(lw[4*c], lw[4*c+1], lw[4*c+2], lw[4*c+3]);
        }
    }

    // ---- weights + node for own particle ----
    {
        const float px = pos[pid * 3 + 0] * 64.f;
        const float py = pos[pid * 3 + 1] * 64.f;
        const float pz = pos[pid * 3 + 2] * 64.f;
        const int bx = (int)px, by = (int)py, bz = (int)pz;
        const float fx = px - (float)bx - 0.5f;
        const float fy = py - (float)by - 0.5f;
        const float fz = pz - (float)bz - 0.5f;
        float* WX = reinterpret_cast<float*>(smem + OFF_WX) + w * 96;
        float* WY = reinterpret_cast<float*>(smem + OFF_WY) + w * 96;
        float* WZ = reinterpret_cast<float*>(smem + OFF_WZ) + w * 96;
        WX[lane]      = 0.5f * (0.5f - fx) * (0.5f - fx);
        WX[32 + lane] = 0.75f - fx * fx;
        WX[64 + lane] = 0.5f * (0.5f + fx) * (0.5f + fx);
        WY[lane]      = 0.5f * (0.5f - fy) * (0.5f - fy);
        WY[32 + lane] = 0.75f - fy * fy;
        WY[64 + lane] = 0.5f * (0.5f + fy) * (0.5f + fy);
        WZ[lane]      = 0.5f * (0.5f - fz) * (0.5f - fz);
        WZ[32 + lane] = 0.75f - fz * fz;
        WZ[64 + lane] = 0.5f * (0.5f + fz) * (0.5f + fz);
        const int b = (pid >= NPERB) ? 1 : 0;
        reinterpret_cast<int*>(smem + OFF_NB)[w * 32 + lane] =
            b * DHW + bx * HWP + by * DD + bz;
    }
    __syncthreads();

    // ---- per-lane constants ----
    float bias_r[4][2];
#pragma unroll
    for (int nb = 0; nb < 4; ++nb) {
        bias_r[nb][0] = bias[nb * 8 + 2 * tig];
        bias_r[nb][1] = bias[nb * 8 + 2 * tig + 1];
    }

    // ---- A fragments (persistent registers) ----
    uint32_t aH[2][2][4], aL[2][2][4];
#pragma unroll
    for (int mb = 0; mb < 2; ++mb)
#pragma unroll
        for (int ks = 0; ks < 2; ++ks) {
            const uint32_t off = (uint32_t)((w * 32 + mb * 16 + (lane & 15)) * 80
                                            + ks * 32 + (lane >> 4) * 16);
            ldm4(aH[mb][ks], sb + OFF_AH + off);
            ldm4(aL[mb][ks], sb + OFF_AL + off);
        }

    const float* WX  = reinterpret_cast<float*>(smem + OFF_WX) + w * 96;
    const float* WY  = reinterpret_cast<float*>(smem + OFF_WY) + w * 96;
    const float* WZ  = reinterpret_cast<float*>(smem + OFF_WZ) + w * 96;
    const int*   NBw = reinterpret_cast<int*>(smem + OFF_NB) + w * 32;
    float* const pbw = reinterpret_cast<float*>(smem + OFF_PB) + w * 1152;  // 32*36

    for (int g = 0; g < 9; ++g) {
        const int oi = g / 3, oj = g % 3;

        // ---- stage B hi/lo for this group's 3 ok taps ----
        __syncthreads();
#pragma unroll
        for (int it = 0; it < 3; ++it) {
            const int idx = it * 128 + tid;
            const int okk = idx >> 7, r = idx & 127;
            const int co = r >> 2, ch = r & 3;
            const uint4* sh = reinterpret_cast<const uint4*>(&g_Bh[g * 3 + okk][co][0]);
            const uint4* sl = reinterpret_cast<const uint4*>(&g_Bl[g * 3 + okk][co][0]);
            reinterpret_cast<uint4*>(smem + OFF_BH + okk * 2560 + co * 80)[ch] = sh[ch];
            reinterpret_cast<uint4*>(smem + OFF_BL + okk * 2560 + co * 80)[ch] = sl[ch];
        }
        __syncthreads();

        float w12[4];
#pragma unroll
        for (int i = 0; i < 4; ++i) {
            const int p = gid + i * 8;
            w12[i] = WX[oi * 32 + p] * WY[oj * 32 + p];
        }

        for (int ok = 0; ok < 3; ++ok) {
            // ---- B fragments ----
            uint32_t bh[4][4], bl[4][4];
#pragma unroll
            for (int nb = 0; nb < 4; ++nb) {
                const uint32_t ba = sb + OFF_BH + (uint32_t)(ok * 2560
                                    + (nb * 8 + (lane & 7)) * 80 + (lane >> 3) * 16);
                ldm4(bh[nb], ba);
                ldm4(bl[nb], ba + (OFF_BL - OFF_BH));
            }

            // ---- 3-term split MMA ----
            float d[2][4][4];
#pragma unroll
            for (int mb = 0; mb < 2; ++mb)
#pragma unroll
                for (int nb = 0; nb < 4; ++nb) {
#pragma unroll
                    for (int q = 0; q < 4; ++q) d[mb][nb][q] = 0.f;
                    mma_bf16(d[mb][nb], aH[mb][0], bh[nb][0], bh[nb][1]);
                    mma_bf16(d[mb][nb], aH[mb][1], bh[nb][2], bh[nb][3]);
                    mma_bf16(d[mb][nb], aH[mb][0], bl[nb][0], bl[nb][1]);
                    mma_bf16(d[mb][nb], aH[mb][1], bl[nb][2], bl[nb][3]);
                    mma_bf16(d[mb][nb], aL[mb][0], bh[nb][0], bh[nb][1]);
                    mma_bf16(d[mb][nb], aL[mb][1], bh[nb][2], bh[nb][3]);
                }

            float w3[4];
#pragma unroll
            for (int i = 0; i < 4; ++i)
                w3[i] = w12[i] * WZ[ok * 32 + gid + i * 8];

            // ---- weighted fragments -> pb [p][co] ----
#pragma unroll
            for (int mb = 0; mb < 2; ++mb)
#pragma unroll
                for (int nb = 0; nb < 4; ++nb) {
                    const int r0 = mb * 16 + gid;
                    const int c  = nb * 8 + 2 * tig;
                    float2 v0, v1;
                    v0.x = (d[mb][nb][0] + bias_r[nb][0]) * w3[mb * 2];
                    v0.y = (d[mb][nb][1] + bias_r[nb][1]) * w3[mb * 2];
                    v1.x = (d[mb][nb][2] + bias_r[nb][0]) * w3[mb * 2 + 1];
                    v1.y = (d[mb][nb][3] + bias_r[nb][1]) * w3[mb * 2 + 1];
                    *reinterpret_cast<float2*>(&pbw[r0 * 36 + c])      = v0;
                    *reinterpret_cast<float2*>(&pbw[(r0 + 8) * 36 + c]) = v1;
                }
            __syncwarp();

            // ---- coalesced float4 REDs into channel-last scratch ----
            const int obase = oi * HWP + oj * DD + ok;
#pragma unroll
            for (int i = 0; i < 8; ++i) {
                const int f = i * 32 + lane;
                const int p = f >> 3, q = f & 7;
                const int nd = NBw[p] + obase;
                const float4 v = *reinterpret_cast<const float4*>(&pbw[p * 36 + q * 4]);
                atomicAdd(reinterpret_cast<float4*>(
                              g_scratch + (size_t)nd * 32 + q * 4), v);
            }
            __syncwarp();
        }
    }
}

// ---------------------------------------------------------------------------
// Transpose scratch [b][node][c] -> out [b][c][node]  (read-only on scratch).
// ---------------------------------------------------------------------------
__global__ void transpose_kernel(float* __restrict__ out) {
    __shared__ float t[32][33];
    const int nd0 = blockIdx.x * 32;
    const int b   = blockIdx.y;
    const int tx  = threadIdx.x, ty = threadIdx.y;
#pragma unroll
    for (int k = 0; k < 4; ++k) {
        const int nd = nd0 + ty + k * 8;
        if (nd < DHW)
            t[ty + k * 8][tx] = g_scratch[((size_t)b * DHW + nd) * 32 + tx];
    }
    __syncthreads();
    const int nd = nd0 + tx;
    if (nd < DHW) {
#pragma unroll
        for (int k = 0; k < 4; ++k) {
            const int c = ty + k * 8;
            out[((size_t)b * 32 + c) * DHW + nd] = t[tx][c];
        }
    }
}

__global__ void zero_scratch_kernel() {
    const size_t n4 = (size_t)2 * DHW * 32 / 4;
    float4* p = reinterpret_cast<float4*>(g_scratch);
    for (size_t i = (size_t)blockIdx.x * blockDim.x + threadIdx.x;
         i < n4; i += (size_t)gridDim.x * blockDim.x)
        p[i] = make_float4(0.f, 0.f, 0.f, 0.f);
}

// ---------------------------------------------------------------------------
extern "C" void kernel_launch(void* const* d_in, const int* in_sizes, int n_in,
                              void* d_out, int out_size)
{
    const float* x    = reinterpret_cast<const float*>(d_in[0]);
    const float* pos  = reinterpret_cast<const float*>(d_in[1]);
    const float* kern = reinterpret_cast<const float*>(d_in[2]);
    const float* bias = reinterpret_cast<const float*>(d_in[3]);
    float* out = reinterpret_cast<float*>(d_out);

    static int attr_done = 0;
    if (!attr_done) {
        cudaFuncSetAttribute(main_kernel,
                             cudaFuncAttributeMaxDynamicSharedMemorySize,
                             SMEM_BYTES);
        attr_done = 1;
    }

    prebuild_kernel<<<27, 256>>>(kern);
    main_kernel<<<NPART / 128, 128, SMEM_BYTES>>>(x, pos, bias);
    transpose_kernel<<<dim3((DHW + 31) / 32, 2), dim3(32, 8)>>>(out);
    zero_scratch_kernel<<<4096, 256>>>();
}

// round 14
// speedup vs baseline: 1.8732x; 1.0548x over previous
#include <cuda_runtime.h>
#include <cstdint>

// Problem: x[2,200000,32] f32, pos[2,200000,3] f32, kernel[3,3,3,32,32] f32,
// bias[32] f32 -> out[2,32,66,66,66] f32.
#define NPART 400000
#define NPERB 200000
#define DD    66
#define HWP   4356
#define DHW   287496

// Channel-last scratch [2*DHW][32]; zero at module load, re-zeroed at end of
// every launch by the standalone zero kernel (proven configuration).
__device__ float g_scratch[(size_t)2 * DHW * 32];          // 73.6 MB

// B operands in MMA *fragment order*: [tap][nb][lane] -> uint4 = 4 packed
// bf16x2 regs (m=0..3). Thread (gid,tig) reg m = B[n=nb*8+gid][k=8m+2tig,+1],
// B[n=co][k=ci] = kern[tap*1024 + ci*32 + co]. One coalesced LDG.128 per nb.
__device__ __align__(16) uint4 g_BfH[27][4][32];
__device__ __align__(16) uint4 g_BfL[27][4][32];

// ---------------- helpers --------------------------------------------------
__device__ __forceinline__ unsigned short f2bf(float f) {
    unsigned short u; asm("cvt.rn.bf16.f32 %0, %1;" : "=h"(u) : "f"(f)); return u;
}
__device__ __forceinline__ float bf2f(unsigned short u) {
    return __uint_as_float(((uint32_t)u) << 16);
}
__device__ __forceinline__ uint32_t smem_u32(const void* p) {
    uint32_t a;
    asm("{ .reg .u64 t; cvta.to.shared.u64 t, %1; cvt.u32.u64 %0, t; }"
        : "=r"(a) : "l"(p));
    return a;
}
__device__ __forceinline__ void ldm4(uint32_t* r, uint32_t addr) {
    asm volatile("ldmatrix.sync.aligned.m8n8.x4.shared.b16 {%0,%1,%2,%3}, [%4];"
                 : "=r"(r[0]), "=r"(r[1]), "=r"(r[2]), "=r"(r[3]) : "r"(addr));
}
__device__ __forceinline__ void mma_bf16(float* d, const uint32_t* a,
                                         uint32_t b0, uint32_t b1) {
    asm volatile(
        "mma.sync.aligned.m16n8k16.row.col.f32.bf16.bf16.f32 "
        "{%0,%1,%2,%3}, {%4,%5,%6,%7}, {%8,%9}, {%0,%1,%2,%3};"
        : "+f"(d[0]), "+f"(d[1]), "+f"(d[2]), "+f"(d[3])
        : "r"(a[0]), "r"(a[1]), "r"(a[2]), "r"(a[3]), "r"(b0), "r"(b1));
}

// ---------------------------------------------------------------------------
// Prebuild: hi/lo bf16 split of kernel, written directly in fragment order.
// 27 blocks x 128 threads (thread = nb*32 + lane).
// ---------------------------------------------------------------------------
__global__ void prebuild_kernel(const float* __restrict__ kern) {
    const int t    = blockIdx.x;          // tap 0..26
    const int nb   = threadIdx.x >> 5;
    const int lane = threadIdx.x & 31;
    const int gid  = lane >> 2, tig = lane & 3;
    const int n    = nb * 8 + gid;        // co
    uint32_t rh[4], rl[4];
#pragma unroll
    for (int m = 0; m < 4; ++m) {
        const int k0 = 8 * m + 2 * tig;   // ci
        const float f0 = kern[(size_t)t * 1024 + k0 * 32 + n];
        const float f1 = kern[(size_t)t * 1024 + (k0 + 1) * 32 + n];
        const unsigned short h0 = f2bf(f0), h1 = f2bf(f1);
        const unsigned short l0 = f2bf(f0 - bf2f(h0)), l1 = f2bf(f1 - bf2f(h1));
        rh[m] = (uint32_t)h0 | ((uint32_t)h1 << 16);
        rl[m] = (uint32_t)l0 | ((uint32_t)l1 << 16);
    }
    g_BfH[t][nb][lane] = make_uint4(rh[0], rh[1], rh[2], rh[3]);
    g_BfL[t][nb][lane] = make_uint4(rl[0], rl[1], rl[2], rl[3]);
}

// ---------------------------------------------------------------------------
// Main kernel: CTA = 4 warps, warp = 32 particles, warps fully independent
// after init (no per-group block barriers). Per (oi,oj,ok): B fragments via
// 8 coalesced LDG.128 (L1-resident after warmup), 3-term bf16-split MMA,
// staged epilogue (pb parity double-buffer, ONE syncwarp per iteration),
// 8 coalesced float4 REDs (4 particles x one FULL 128B line each).
// ---------------------------------------------------------------------------
#define OFF_AH 0
#define OFF_AL 10240
#define OFF_WX 20480
#define OFF_WY 22016
#define OFF_WZ 23552
#define OFF_NB 25088
#define OFF_PB 25600
#define SMEM_BYTES (OFF_PB + 4 * 2 * 1152 * 4)   // 62464

__global__ __launch_bounds__(128) void main_kernel(
    const float* __restrict__ x,
    const float* __restrict__ pos,
    const float* __restrict__ bias)
{
    extern __shared__ __align__(16) char smem[];
    const int tid  = threadIdx.x;
    const int w    = tid >> 5;
    const int lane = tid & 31;
    const int gid  = lane >> 2;          // fragment row id
    const int tig  = lane & 3;           // thread-in-group (col pair)
    const int pid  = blockIdx.x * 128 + w * 32 + lane;
    const uint32_t sb = smem_u32(smem);

    // ---- stage A: x -> bf16 hi/lo rows (80B stride, conflict-free) ----
    {
        float xv[32];
        const float4* xp = reinterpret_cast<const float4*>(x + (size_t)pid * 32);
#pragma unroll
        for (int t = 0; t < 8; ++t) {
            const float4 v = xp[t];
            xv[4 * t] = v.x; xv[4 * t + 1] = v.y; xv[4 * t + 2] = v.z; xv[4 * t + 3] = v.w;
        }
        uint32_t hw[16], lw[16];
#pragma unroll
        for (int k = 0; k < 16; ++k) {
            const float f0 = xv[2 * k], f1 = xv[2 * k + 1];
            const unsigned short h0 = f2bf(f0), h1 = f2bf(f1);
            const unsigned short l0 = f2bf(f0 - bf2f(h0)), l1 = f2bf(f1 - bf2f(h1));
            hw[k] = (uint32_t)h0 | ((uint32_t)h1 << 16);
            lw[k] = (uint32_t)l0 | ((uint32_t)l1 << 16);
        }
        char* rH = smem + OFF_AH + (w * 32 + lane) * 80;
        char* rL = smem + OFF_AL + (w * 32 + lane) * 80;
#pragma unroll
        for (int c = 0; c < 4; ++c) {
            reinterpret_cast<uint4*>(rH)[c] = make_uint4(hw[4*c], hw[4*c+1], hw[4*c+2], hw[4*c+3]);
            reinterpret_cast<uint4*>(rL)[c] = make_uint4(lw[4*c], lw[4*c+1], lw[4*c+2], lw[4*c+3]);
        }
    }

    // ---- weights + node for own particle ----
    {
        const float px = pos[pid * 3 + 0] * 64.f;
        const float py = pos[pid * 3 + 1] * 64.f;
        const float pz = pos[pid * 3 + 2] * 64.f;
        const int bx = (int)px, by = (int)py, bz = (int)pz;
        const float fx = px - (float)bx - 0.5f;
        const float fy = py - (float)by - 0.5f;
        const float fz = pz - (float)bz - 0.5f;
        float* WX = reinterpret_cast<float*>(smem + OFF_WX) + w * 96;
        float* WY = reinterpret_cast<float*>(smem + OFF_WY) + w * 96;
        float* WZ = reinterpret_cast<float*>(smem + OFF_WZ) + w * 96;
        WX[lane]      = 0.5f * (0.5f - fx) * (0.5f - fx);
        WX[32 + lane] = 0.75f - fx * fx;
        WX[64 + lane] = 0.5f * (0.5f + fx) * (0.5f + fx);
        WY[lane]      = 0.5f * (0.5f - fy) * (0.5f - fy);
        WY[32 + lane] = 0.75f - fy * fy;
        WY[64 + lane] = 0.5f * (0.5f + fy) * (0.5f + fy);
        WZ[lane]      = 0.5f * (0.5f - fz) * (0.5f - fz);
        WZ[32 + lane] = 0.75f - fz * fz;
        WZ[64 + lane] = 0.5f * (0.5f + fz) * (0.5f + fz);
        const int b = (pid >= NPERB) ? 1 : 0;
        reinterpret_cast<int*>(smem + OFF_NB)[w * 32 + lane] =
            b * DHW + bx * HWP + by * DD + bz;
    }
    __syncwarp();    // all staged data is per-warp; warps stay independent

    // ---- per-lane constants ----
    float bias_r[4][2];
#pragma unroll
    for (int nb = 0; nb < 4; ++nb) {
        bias_r[nb][0] = bias[nb * 8 + 2 * tig];
        bias_r[nb][1] = bias[nb * 8 + 2 * tig + 1];
    }

    // ---- A fragments (persistent registers) ----
    uint32_t aH[2][2][4], aL[2][2][4];
#pragma unroll
    for (int mb = 0; mb < 2; ++mb)
#pragma unroll
        for (int ks = 0; ks < 2; ++ks) {
            const uint32_t off = (uint32_t)((w * 32 + mb * 16 + (lane & 15)) * 80
                                            + ks * 32 + (lane >> 4) * 16);
            ldm4(aH[mb][ks], sb + OFF_AH + off);
            ldm4(aL[mb][ks], sb + OFF_AL + off);
        }

    const float* WX  = reinterpret_cast<float*>(smem + OFF_WX) + w * 96;
    const float* WY  = reinterpret_cast<float*>(smem + OFF_WY) + w * 96;
    const float* WZ  = reinterpret_cast<float*>(smem + OFF_WZ) + w * 96;
    const int*   NBw = reinterpret_cast<int*>(smem + OFF_NB) + w * 32;
    float* const pb0 = reinterpret_cast<float*>(smem + OFF_PB) + w * 2304; // 2x1152

    for (int g = 0; g < 9; ++g) {
        const int oi = g / 3, oj = g % 3;

        float w12[4];
#pragma unroll
        for (int i = 0; i < 4; ++i) {
            const int p = gid + i * 8;
            w12[i] = WX[oi * 32 + p] * WY[oj * 32 + p];
        }

        for (int ok = 0; ok < 3; ++ok) {
            // ---- B fragments: direct coalesced LDG.128 (fragment order) ----
            const int tap = g * 3 + ok;
            uint4 bhv[4], blv[4];
#pragma unroll
            for (int nb = 0; nb < 4; ++nb) {
                bhv[nb] = g_BfH[tap][nb][lane];
                blv[nb] = g_BfL[tap][nb][lane];
            }
            const uint32_t* bh = reinterpret_cast<const uint32_t*>(bhv);
            const uint32_t* bl = reinterpret_cast<const uint32_t*>(blv);

            // ---- 3-term split MMA ----
            float d[2][4][4];
#pragma unroll
            for (int mb = 0; mb < 2; ++mb)
#pragma unroll
                for (int nb = 0; nb < 4; ++nb) {
#pragma unroll
                    for (int q = 0; q < 4; ++q) d[mb][nb][q] = 0.f;
                    mma_bf16(d[mb][nb], aH[mb][0], bh[nb * 4 + 0], bh[nb * 4 + 1]);
                    mma_bf16(d[mb][nb], aH[mb][1], bh[nb * 4 + 2], bh[nb * 4 + 3]);
                    mma_bf16(d[mb][nb], aH[mb][0], bl[nb * 4 + 0], bl[nb * 4 + 1]);
                    mma_bf16(d[mb][nb], aH[mb][1], bl[nb * 4 + 2], bl[nb * 4 + 3]);
                    mma_bf16(d[mb][nb], aL[mb][0], bh[nb * 4 + 0], bh[nb * 4 + 1]);
                    mma_bf16(d[mb][nb], aL[mb][1], bh[nb * 4 + 2], bh[nb * 4 + 3]);
                }

            float w3[4];
#pragma unroll
            for (int i = 0; i < 4; ++i)
                w3[i] = w12[i] * WZ[ok * 32 + gid + i * 8];

            // ---- weighted fragments -> pb [p][co], parity double-buffered ----
            float* const pbw = pb0 + ((g * 3 + ok) & 1) * 1152;
#pragma unroll
            for (int mb = 0; mb < 2; ++mb)
#pragma unroll
                for (int nb = 0; nb < 4; ++nb) {
                    const int r0 = mb * 16 + gid;
                    const int c  = nb * 8 + 2 * tig;
                    float2 v0, v1;
                    v0.x = (d[mb][nb][0] + bias_r[nb][0]) * w3[mb * 2];
                    v0.y = (d[mb][nb][1] + bias_r[nb][1]) * w3[mb * 2];
                    v1.x = (d[mb][nb][2] + bias_r[nb][0]) * w3[mb * 2 + 1];
                    v1.y = (d[mb][nb][3] + bias_r[nb][1]) * w3[mb * 2 + 1];
                    *reinterpret_cast<float2*>(&pbw[r0 * 36 + c])       = v0;
                    *reinterpret_cast<float2*>(&pbw[(r0 + 8) * 36 + c]) = v1;
                }
            __syncwarp();

            // ---- coalesced float4 REDs (4 particles x full 128B line each) ----
            const int obase = oi * HWP + oj * DD + ok;
#pragma unroll
            for (int i = 0; i < 8; ++i) {
                const int f = i * 32 + lane;
                const int p = f >> 3, q = f & 7;
                const int nd = NBw[p] + obase;
                const float4 v = *reinterpret_cast<const float4*>(&pbw[p * 36 + q * 4]);
                atomicAdd(reinterpret_cast<float4*>(
                              g_scratch + (size_t)nd * 32 + q * 4), v);
            }
            // no trailing syncwarp: next iteration writes the OTHER pb buffer;
            // this buffer's next write is separated by that iteration's syncwarp.
        }
    }
}

// ---------------------------------------------------------------------------
// Transpose scratch [b][node][c] -> out [b][c][node]  (read-only on scratch).
// ---------------------------------------------------------------------------
__global__ void transpose_kernel(float* __restrict__ out) {
    __shared__ float t[32][33];
    const int nd0 = blockIdx.x * 32;
    const int b   = blockIdx.y;
    const int tx  = threadIdx.x, ty = threadIdx.y;
#pragma unroll
    for (int k = 0; k < 4; ++k) {
        const int nd = nd0 + ty + k * 8;
        if (nd < DHW)
            t[ty + k * 8][tx] = g_scratch[((size_t)b * DHW + nd) * 32 + tx];
    }
    __syncthreads();
    const int nd = nd0 + tx;
    if (nd < DHW) {
#pragma unroll
        for (int k = 0; k < 4; ++k) {
            const int c = ty + k * 8;
            out[((size_t)b * 32 + c) * DHW + nd] = t[tx][c];
        }
    }
}

__global__ void zero_scratch_kernel() {
    const size_t n4 = (size_t)2 * DHW * 32 / 4;
    float4* p = reinterpret_cast<float4*>(g_scratch);
    for (size_t i = (size_t)blockIdx.x * blockDim.x + threadIdx.x;
         i < n4; i += (size_t)gridDim.x * blockDim.x)
        p[i] = make_float4(0.f, 0.f, 0.f, 0.f);
}

// ---------------------------------------------------------------------------
extern "C" void kernel_launch(void* const* d_in, const int* in_sizes, int n_in,
                              void* d_out, int out_size)
{
    const float* x    = reinterpret_cast<const float*>(d_in[0]);
    const float* pos  = reinterpret_cast<const float*>(d_in[1]);
    const float* kern = reinterpret_cast<const float*>(d_in[2]);
    const float* bias = reinterpret_cast<const float*>(d_in[3]);
    float* out = reinterpret_cast<float*>(d_out);

    static int attr_done = 0;
    if (!attr_done) {
        cudaFuncSetAttribute(main_kernel,
                             cudaFuncAttributeMaxDynamicSharedMemorySize,
                             SMEM_BYTES);
        attr_done = 1;
    }

    prebuild_kernel<<<27, 128>>>(kern);
    main_kernel<<<NPART / 128, 128, SMEM_BYTES>>>(x, pos, bias);
    transpose_kernel<<<dim3((DHW + 31) / 32, 2), dim3(32, 8)>>>(out);
    zero_scratch_kernel<<<4096, 256>>>();
}

// round 15
// speedup vs baseline: 1.9400x; 1.0357x over previous
#include <cuda_runtime.h>
#include <cstdint>

// Problem: x[2,200000,32] f32, pos[2,200000,3] f32, kernel[3,3,3,32,32] f32,
// bias[32] f32 -> out[2,32,66,66,66] f32.
#define NPART 400000
#define NPERB 200000
#define DD    66
#define HWP   4356
#define DHW   287496

// Channel-last scratch [2*DHW][32]; zero at module load, re-zeroed at end of
// every launch by the standalone zero kernel (proven configuration).
__device__ float g_scratch[(size_t)2 * DHW * 32];          // 73.6 MB

// B operands in MMA *fragment order*: [tap][nb][lane] -> uint4 = 4 packed
// bf16x2 regs (m=0..3). Thread (gid,tig) reg m = B[n=nb*8+gid][k=8m+2tig,+1].
__device__ __align__(16) uint4 g_BfH[27][4][32];
__device__ __align__(16) uint4 g_BfL[27][4][32];

// ---------------- helpers --------------------------------------------------
__device__ __forceinline__ unsigned short f2bf(float f) {
    unsigned short u; asm("cvt.rn.bf16.f32 %0, %1;" : "=h"(u) : "f"(f)); return u;
}
__device__ __forceinline__ float bf2f(unsigned short u) {
    return __uint_as_float(((uint32_t)u) << 16);
}
__device__ __forceinline__ uint32_t smem_u32(const void* p) {
    uint32_t a;
    asm("{ .reg .u64 t; cvta.to.shared.u64 t, %1; cvt.u32.u64 %0, t; }"
        : "=r"(a) : "l"(p));
    return a;
}
__device__ __forceinline__ void ldm4(uint32_t* r, uint32_t addr) {
    asm volatile("ldmatrix.sync.aligned.m8n8.x4.shared.b16 {%0,%1,%2,%3}, [%4];"
                 : "=r"(r[0]), "=r"(r[1]), "=r"(r[2]), "=r"(r[3]) : "r"(addr));
}
__device__ __forceinline__ void mma_bf16(float* d, const uint32_t* a,
                                         uint32_t b0, uint32_t b1) {
    asm volatile(
        "mma.sync.aligned.m16n8k16.row.col.f32.bf16.bf16.f32 "
        "{%0,%1,%2,%3}, {%4,%5,%6,%7}, {%8,%9}, {%0,%1,%2,%3};"
        : "+f"(d[0]), "+f"(d[1]), "+f"(d[2]), "+f"(d[3])
        : "r"(a[0]), "r"(a[1]), "r"(a[2]), "r"(a[3]), "r"(b0), "r"(b1));
}

// ---------------------------------------------------------------------------
// Prebuild: hi/lo bf16 split of kernel, written directly in fragment order.
// ---------------------------------------------------------------------------
__global__ void prebuild_kernel(const float* __restrict__ kern) {
    const int t    = blockIdx.x;          // tap 0..26
    const int nb   = threadIdx.x >> 5;
    const int lane = threadIdx.x & 31;
    const int gid  = lane >> 2, tig = lane & 3;
    const int n    = nb * 8 + gid;        // co
    uint32_t rh[4], rl[4];
#pragma unroll
    for (int m = 0; m < 4; ++m) {
        const int k0 = 8 * m + 2 * tig;   // ci
        const float f0 = kern[(size_t)t * 1024 + k0 * 32 + n];
        const float f1 = kern[(size_t)t * 1024 + (k0 + 1) * 32 + n];
        const unsigned short h0 = f2bf(f0), h1 = f2bf(f1);
        const unsigned short l0 = f2bf(f0 - bf2f(h0)), l1 = f2bf(f1 - bf2f(h1));
        rh[m] = (uint32_t)h0 | ((uint32_t)h1 << 16);
        rl[m] = (uint32_t)l0 | ((uint32_t)l1 << 16);
    }
    g_BfH[t][nb][lane] = make_uint4(rh[0], rh[1], rh[2], rh[3]);
    g_BfL[t][nb][lane] = make_uint4(rl[0], rl[1], rl[2], rl[3]);
}

// ---------------------------------------------------------------------------
// Main kernel (R14 + nb8 hoist): CTA = 4 independent warps, warp = 32
// particles. Per (oi,oj,ok): B fragments via coalesced LDG.128 (L1-resident),
// 3-term bf16-split MMA, staged epilogue (parity double-buffer, one syncwarp),
// 8 coalesced float4 REDs (4 particles x one FULL 128B line each).
// ---------------------------------------------------------------------------
#define OFF_AH 0
#define OFF_AL 10240
#define OFF_WX 20480
#define OFF_WY 22016
#define OFF_WZ 23552
#define OFF_NB 25088
#define OFF_PB 25600
#define SMEM_BYTES (OFF_PB + 4 * 2 * 1152 * 4)   // 62464

__global__ __launch_bounds__(128) void main_kernel(
    const float* __restrict__ x,
    const float* __restrict__ pos,
    const float* __restrict__ bias)
{
    extern __shared__ __align__(16) char smem[];
    const int tid  = threadIdx.x;
    const int w    = tid >> 5;
    const int lane = tid & 31;
    const int gid  = lane >> 2;          // fragment row id
    const int tig  = lane & 3;           // thread-in-group (col pair)
    const int pid  = blockIdx.x * 128 + w * 32 + lane;
    const uint32_t sb = smem_u32(smem);

    // ---- stage A: x -> bf16 hi/lo rows (80B stride, conflict-free) ----
    {
        float xv[32];
        const float4* xp = reinterpret_cast<const float4*>(x + (size_t)pid * 32);
#pragma unroll
        for (int t = 0; t < 8; ++t) {
            const float4 v = xp[t];
            xv[4 * t] = v.x; xv[4 * t + 1] = v.y; xv[4 * t + 2] = v.z; xv[4 * t + 3] = v.w;
        }
        uint32_t hw[16], lw[16];
#pragma unroll
        for (int k = 0; k < 16; ++k) {
            const float f0 = xv[2 * k], f1 = xv[2 * k + 1];
            const unsigned short h0 = f2bf(f0), h1 = f2bf(f1);
            const unsigned short l0 = f2bf(f0 - bf2f(h0)), l1 = f2bf(f1 - bf2f(h1));
            hw[k] = (uint32_t)h0 | ((uint32_t)h1 << 16);
            lw[k] = (uint32_t)l0 | ((uint32_t)l1 << 16);
        }
        char* rH = smem + OFF_AH + (w * 32 + lane) * 80;
        char* rL = smem + OFF_AL + (w * 32 + lane) * 80;
#pragma unroll
        for (int c = 0; c < 4; ++c) {
            reinterpret_cast<uint4*>(rH)[c] = make_uint4(hw[4*c], hw[4*c+1], hw[4*c+2], hw[4*c+3]);
            reinterpret_cast<uint4*>(rL)[c] = make_uint4(lw[4*c], lw[4*c+1], lw[4*c+2], lw[4*c+3]);
        }
    }

    // ---- weights + node for own particle ----
    {
        const float px = pos[pid * 3 + 0] * 64.f;
        const float py = pos[pid * 3 + 1] * 64.f;
        const float pz = pos[pid * 3 + 2] * 64.f;
        const int bx = (int)px, by = (int)py, bz = (int)pz;
        const float fx = px - (float)bx - 0.5f;
        const float fy = py - (float)by - 0.5f;
        const float fz = pz - (float)bz - 0.5f;
        float* WX = reinterpret_cast<float*>(smem + OFF_WX) + w * 96;
        float* WY = reinterpret_cast<float*>(smem + OFF_WY) + w * 96;
        float* WZ = reinterpret_cast<float*>(smem + OFF_WZ) + w * 96;
        WX[lane]      = 0.5f * (0.5f - fx) * (0.5f - fx);
        WX[32 + lane] = 0.75f - fx * fx;
        WX[64 + lane] = 0.5f * (0.5f + fx) * (0.5f + fx);
        WY[lane]      = 0.5f * (0.5f - fy) * (0.5f - fy);
        WY[32 + lane] = 0.75f - fy * fy;
        WY[64 + lane] = 0.5f * (0.5f + fy) * (0.5f + fy);
        WZ[lane]      = 0.5f * (0.5f - fz) * (0.5f - fz);
        WZ[32 + lane] = 0.75f - fz * fz;
        WZ[64 + lane] = 0.5f * (0.5f + fz) * (0.5f + fz);
        const int b = (pid >= NPERB) ? 1 : 0;
        reinterpret_cast<int*>(smem + OFF_NB)[w * 32 + lane] =
            b * DHW + bx * HWP + by * DD + bz;
    }
    __syncwarp();    // all staged data is per-warp; warps stay independent

    // ---- per-lane constants ----
    float bias_r[4][2];
#pragma unroll
    for (int nb = 0; nb < 4; ++nb) {
        bias_r[nb][0] = bias[nb * 8 + 2 * tig];
        bias_r[nb][1] = bias[nb * 8 + 2 * tig + 1];
    }

    // ---- A fragments (persistent registers) ----
    uint32_t aH[2][2][4], aL[2][2][4];
#pragma unroll
    for (int mb = 0; mb < 2; ++mb)
#pragma unroll
        for (int ks = 0; ks < 2; ++ks) {
            const uint32_t off = (uint32_t)((w * 32 + mb * 16 + (lane & 15)) * 80
                                            + ks * 32 + (lane >> 4) * 16);
            ldm4(aH[mb][ks], sb + OFF_AH + off);
            ldm4(aL[mb][ks], sb + OFF_AL + off);
        }

    const float* WX  = reinterpret_cast<float*>(smem + OFF_WX) + w * 96;
    const float* WY  = reinterpret_cast<float*>(smem + OFF_WY) + w * 96;
    const float* WZ  = reinterpret_cast<float*>(smem + OFF_WZ) + w * 96;
    const int*   NBw = reinterpret_cast<int*>(smem + OFF_NB) + w * 32;
    float* const pb0 = reinterpret_cast<float*>(smem + OFF_PB) + w * 2304; // 2x1152

    // ---- RED node bases: this thread's 8 p-slots are fixed (p=lane>>3 + 4i).
    int nb8[8];
#pragma unroll
    for (int i = 0; i < 8; ++i) nb8[i] = NBw[(lane >> 3) + 4 * i];

    for (int g = 0; g < 9; ++g) {
        const int oi = g / 3, oj = g % 3;

        float w12[4];
#pragma unroll
        for (int i = 0; i < 4; ++i) {
            const int p = gid + i * 8;
            w12[i] = WX[oi * 32 + p] * WY[oj * 32 + p];
        }

        for (int ok = 0; ok < 3; ++ok) {
            // ---- B fragments: direct coalesced LDG.128 (fragment order) ----
            const int tap = g * 3 + ok;
            uint4 bhv[4], blv[4];
#pragma unroll
            for (int nb = 0; nb < 4; ++nb) {
                bhv[nb] = g_BfH[tap][nb][lane];
                blv[nb] = g_BfL[tap][nb][lane];
            }
            const uint32_t* bh = reinterpret_cast<const uint32_t*>(bhv);
            const uint32_t* bl = reinterpret_cast<const uint32_t*>(blv);

            // ---- 3-term split MMA ----
            float d[2][4][4];
#pragma unroll
            for (int mb = 0; mb < 2; ++mb)
#pragma unroll
                for (int nb = 0; nb < 4; ++nb) {
#pragma unroll
                    for (int q = 0; q < 4; ++q) d[mb][nb][q] = 0.f;
                    mma_bf16(d[mb][nb], aH[mb][0], bh[nb * 4 + 0], bh[nb * 4 + 1]);
                    mma_bf16(d[mb][nb], aH[mb][1], bh[nb * 4 + 2], bh[nb * 4 + 3]);
                    mma_bf16(d[mb][nb], aH[mb][0], bl[nb * 4 + 0], bl[nb * 4 + 1]);
                    mma_bf16(d[mb][nb], aH[mb][1], bl[nb * 4 + 2], bl[nb * 4 + 3]);
                    mma_bf16(d[mb][nb], aL[mb][0], bh[nb * 4 + 0], bh[nb * 4 + 1]);
                    mma_bf16(d[mb][nb], aL[mb][1], bh[nb * 4 + 2], bh[nb * 4 + 3]);
                }

            float w3[4];
#pragma unroll
            for (int i = 0; i < 4; ++i)
                w3[i] = w12[i] * WZ[ok * 32 + gid + i * 8];

            // ---- weighted fragments -> pb [p][co], parity double-buffered ----
            float* const pbw = pb0 + ((g * 3 + ok) & 1) * 1152;
#pragma unroll
            for (int mb = 0; mb < 2; ++mb)
#pragma unroll
                for (int nb = 0; nb < 4; ++nb) {
                    const int r0 = mb * 16 + gid;
                    const int c  = nb * 8 + 2 * tig;
                    float2 v0, v1;
                    v0.x = (d[mb][nb][0] + bias_r[nb][0]) * w3[mb * 2];
                    v0.y = (d[mb][nb][1] + bias_r[nb][1]) * w3[mb * 2];
                    v1.x = (d[mb][nb][2] + bias_r[nb][0]) * w3[mb * 2 + 1];
                    v1.y = (d[mb][nb][3] + bias_r[nb][1]) * w3[mb * 2 + 1];
                    *reinterpret_cast<float2*>(&pbw[r0 * 36 + c])       = v0;
                    *reinterpret_cast<float2*>(&pbw[(r0 + 8) * 36 + c]) = v1;
                }
            __syncwarp();

            // ---- coalesced float4 REDs (4 particles x full 128B line each) ----
            const int obase = oi * HWP + oj * DD + ok;
#pragma unroll
            for (int i = 0; i < 8; ++i) {
                const int f = i * 32 + lane;
                const int p = f >> 3, q = f & 7;
                const int nd = nb8[i] + obase;            // register, no LDS
                const float4 v = *reinterpret_cast<const float4*>(&pbw[p * 36 + q * 4]);
                atomicAdd(reinterpret_cast<float4*>(
                              g_scratch + (size_t)nd * 32 + q * 4), v);
            }
            // no trailing syncwarp (parity double-buffer).
        }
    }
}

// ---------------------------------------------------------------------------
// Transpose scratch [b][node][c] -> out [b][c][node]  (read-only on scratch).
// R15: one LDG.128 per thread (4 channels of one node), conflict-aware smem
// stage, coalesced 128B row writes.
// ---------------------------------------------------------------------------
__global__ void transpose_kernel(float* __restrict__ out) {
    __shared__ float t[32][33];
    const int tid = threadIdx.x;          // 256
    const int b   = blockIdx.y;
    const int nd0 = blockIdx.x * 32;

    // Load: thread = (ty=tid/8 node, tx=tid%8 channel-quad): one float4.
    {
        const int ty = tid >> 3, tx = tid & 7;
        const int nd = nd0 + ty;
        if (nd < DHW) {
            const float4 v = *reinterpret_cast<const float4*>(
                &g_scratch[((size_t)b * DHW + nd) * 32 + 4 * tx]);
            t[ty][4 * tx + 0] = v.x;
            t[ty][4 * tx + 1] = v.y;
            t[ty][4 * tx + 2] = v.z;
            t[ty][4 * tx + 3] = v.w;
        }
    }
    __syncthreads();

    // Write: c0 = tid/32, n = tid%32; 4 channels per thread, 128B rows.
    const int c0 = tid >> 5, n = tid & 31;
    const int nd = nd0 + n;
    if (nd < DHW) {
#pragma unroll
        for (int k = 0; k < 4; ++k) {
            const int c = c0 + 8 * k;
            out[((size_t)b * 32 + c) * DHW + nd] = t[n][c];   // conflict-free LDS
        }
    }
}

__global__ void zero_scratch_kernel() {
    const size_t n4 = (size_t)2 * DHW * 32 / 4;
    float4* p = reinterpret_cast<float4*>(g_scratch);
    for (size_t i = (size_t)blockIdx.x * blockDim.x + threadIdx.x;
         i < n4; i += (size_t)gridDim.x * blockDim.x)
        p[i] = make_float4(0.f, 0.f, 0.f, 0.f);
}

// ---------------------------------------------------------------------------
extern "C" void kernel_launch(void* const* d_in, const int* in_sizes, int n_in,
                              void* d_out, int out_size)
{
    const float* x    = reinterpret_cast<const float*>(d_in[0]);
    const float* pos  = reinterpret_cast<const float*>(d_in[1]);
    const float* kern = reinterpret_cast<const float*>(d_in[2]);
    const float* bias = reinterpret_cast<const float*>(d_in[3]);
    float* out = reinterpret_cast<float*>(d_out);

    static int attr_done = 0;
    if (!attr_done) {
        cudaFuncSetAttribute(main_kernel,
                             cudaFuncAttributeMaxDynamicSharedMemorySize,
                             SMEM_BYTES);
        attr_done = 1;
    }

    prebuild_kernel<<<27, 128>>>(kern);
    main_kernel<<<NPART / 128, 128, SMEM_BYTES>>>(x, pos, bias);
    transpose_kernel<<<dim3((DHW + 31) / 32, 2), 256>>>(out);
    zero_scratch_kernel<<<4096, 256>>>();
}